// round 14
// baseline (speedup 1.0000x reference)
#include <cuda_runtime.h>
#include <cuda_fp16.h>
#include <cstdint>
#include <math.h>

// ---------------- problem constants (fixed by reference) ----------------
#define NN      100000      // N_NODES
#define NE      1600000     // N_EDGES
#define HID     64
#define INC     256
#define OUTC    32
#define KORD    10
#define NLAYERS 2
#define NBLK_SCAN 391       // ceil(NN/256)
#define PROP_TPB 256        // 8 warps (nodes) per block: fewer CTAs/SM at the
                            // same warp count -> less cross-CTA L1tex-queue
                            // spread (B300 spr model). Warp-level code identical.
#define NBLK_PROP (NN / 8)  // 12500
#define NEP_MAX (NE + 8 * NN)   // padded CSR capacity (2.4M)

// ---------------- device scratch (static globals: allowed) --------------
__device__ int   g_is64;
__device__ int   g_deg[NN];
__device__ float g_dinv[NN];        // 1/sqrt(deg+1)
__device__ float g_ds[NN];          // sqrt(deg+1)
__device__ int   g_off[NN + 1];     // padded-CSR offsets (multiples of 8)
__device__ int   g_cur[NN];
__device__ __align__(16) int g_src[NEP_MAX];
__device__ int   g_bsum[512];

// slot k holds dinv * t_k as half2 (32 half2 = 64 ch per node).
// Row NN is the zero sentinel row for CSR padding — never written.
__device__ __align__(16) __half2 g_H[KORD + 1][(NN + 8) * 32];

// ============== dtype detect + zero deg + src sentinel fill (fused) =====
__global__ void zero_detect_kernel(const int* __restrict__ ei32) {
    int i = blockIdx.x * 256 + threadIdx.x;
    if (i < NN) g_deg[i] = 0;
    if (i < NEP_MAX / 4)
        *(int4*)&g_src[i * 4] = make_int4(NN, NN, NN, NN);
    if (blockIdx.x == 0) {
        __shared__ int nz;
        if (threadIdx.x == 0) nz = 0;
        __syncthreads();
        for (int t = threadIdx.x; t < 4096; t += 256)
            if (ei32[2 * t + 1] != 0) nz = 1;
        __syncthreads();
        if (threadIdx.x == 0) g_is64 = nz ? 0 : 1;
    }
}

// ======================= CSR build (vectorized, 4 edges/thread) =========

__device__ __forceinline__ int4 edge4_at(const void* __restrict__ ei, int base, int is64) {
    if (is64) {
        const longlong2* p = (const longlong2*)((const long long*)ei + base);
        longlong2 a = p[0], b = p[1];
        return make_int4((int)a.x, (int)a.y, (int)b.x, (int)b.y);
    }
    return *(const int4*)((const int*)ei + base);
}

__global__ void count_deg_kernel(const void* __restrict__ ei) {
    int is64 = g_is64;
    int e4 = blockIdx.x * 256 + threadIdx.x;
    if (e4 < NE / 4) {
        int4 c = edge4_at(ei, NE + e4 * 4, is64);
        atomicAdd(&g_deg[c.x], 1);
        atomicAdd(&g_deg[c.y], 1);
        atomicAdd(&g_deg[c.z], 1);
        atomicAdd(&g_deg[c.w], 1);
    }
}

// scan of PADDED degrees (rounded up to multiple of 8); dinv/ds from real deg
__global__ void scan1_kernel() {
    __shared__ int sh[256];
    int tid = threadIdx.x;
    int i = blockIdx.x * 256 + tid;
    int v = (i < NN) ? g_deg[i] : 0;
    if (i < NN) {
        float d = (float)(v + 1);
        g_dinv[i] = rsqrtf(d);
        g_ds[i]   = sqrtf(d);
    }
    int pv = (v + 7) & ~7;                   // padded degree
    sh[tid] = pv;
    __syncthreads();
#pragma unroll
    for (int o = 1; o < 256; o <<= 1) {
        int t = (tid >= o) ? sh[tid - o] : 0;
        __syncthreads();
        sh[tid] += t;
        __syncthreads();
    }
    if (i < NN) g_off[i] = sh[tid] - pv;
    if (tid == 255) g_bsum[blockIdx.x] = sh[255];
}

__global__ void scan23_kernel() {
    __shared__ int sh[512];
    int tid = threadIdx.x;
    int v = (tid < NBLK_SCAN) ? g_bsum[tid] : 0;
    sh[tid] = v;
    __syncthreads();
#pragma unroll
    for (int o = 1; o < 512; o <<= 1) {
        int t = (tid >= o) ? sh[tid - o] : 0;
        __syncthreads();
        sh[tid] += t;
        __syncthreads();
    }
    int i = blockIdx.x * 512 + tid;
    if (i < NN) {
        int sb = i >> 8;
        int add = (sb > 0) ? sh[sb - 1] : 0;
        int o = g_off[i] + add;
        g_off[i] = o;
        g_cur[i] = o;
    }
    if (blockIdx.x == 0 && tid == 0) g_off[NN] = sh[NBLK_SCAN - 1];  // total padded
}

__global__ void scatter_kernel(const void* __restrict__ ei) {
    int is64 = g_is64;
    int e4 = blockIdx.x * 256 + threadIdx.x;
    if (e4 < NE / 4) {
        int4 r = edge4_at(ei, e4 * 4, is64);
        int4 c = edge4_at(ei, NE + e4 * 4, is64);
        g_src[atomicAdd(&g_cur[c.x], 1)] = r.x;
        g_src[atomicAdd(&g_cur[c.y], 1)] = r.y;
        g_src[atomicAdd(&g_cur[c.z], 1)] = r.z;
        g_src[atomicAdd(&g_cur[c.w], 1)] = r.w;
    }
}

// ======================= GEMM1 (tensor cores, fp16 in / fp32 acc) ========
// g_H[0] = half(dinv * relu(x @ W1 + b1)).  KC=32 (R11 form).

#define KC 32

__global__ __launch_bounds__(128) void gemm1_kernel(const float* __restrict__ x,
                                                    const float* __restrict__ W1,
                                                    const float* __restrict__ b1) {
    __shared__ __align__(16) __half As[64][KC + 8];
    __shared__ __align__(16) __half Bs[64][KC + 8];
    __shared__ float bsh[64];
    int tid = threadIdx.x;
    int warp = tid >> 5, lane = tid & 31;
    int g = lane >> 2;
    int t2 = (lane & 3) * 2;
    int row0 = blockIdx.x * 64;

    if (tid < 64) bsh[tid] = b1[tid];

    float acc[8][4];
#pragma unroll
    for (int nt = 0; nt < 8; nt++)
#pragma unroll
        for (int q = 0; q < 4; q++) acc[nt][q] = 0.f;

    for (int kc = 0; kc < INC; kc += KC) {
        {
            int r = tid >> 1;
            int kp = (tid & 1) * 16;
            int gr = row0 + r;
            const float4* xr = (const float4*)(x + (long long)gr * INC + kc + kp);
            float4 v[4];
#pragma unroll
            for (int q = 0; q < 4; q++)
                v[q] = (gr < NN) ? xr[q] : make_float4(0.f, 0.f, 0.f, 0.f);
            __half2* dst = (__half2*)&As[r][kp];
#pragma unroll
            for (int q = 0; q < 4; q++) {
                dst[q * 2 + 0] = __floats2half2_rn(v[q].x, v[q].y);
                dst[q * 2 + 1] = __floats2half2_rn(v[q].z, v[q].w);
            }
        }
        for (int q = 0; q < 4; q++) {
            int idx = tid + 128 * q;
            int k = idx >> 4;
            int n0 = (idx & 15) * 4;
            float4 wv = *(const float4*)(W1 + (long long)(kc + k) * HID + n0);
            Bs[n0 + 0][k] = __float2half_rn(wv.x);
            Bs[n0 + 1][k] = __float2half_rn(wv.y);
            Bs[n0 + 2][k] = __float2half_rn(wv.z);
            Bs[n0 + 3][k] = __float2half_rn(wv.w);
        }
        __syncthreads();

#pragma unroll
        for (int kk = 0; kk < KC; kk += 16) {
            uint32_t a0 = *(const uint32_t*)&As[16 * warp + g    ][kk + t2];
            uint32_t a1 = *(const uint32_t*)&As[16 * warp + g + 8][kk + t2];
            uint32_t a2 = *(const uint32_t*)&As[16 * warp + g    ][kk + t2 + 8];
            uint32_t a3 = *(const uint32_t*)&As[16 * warp + g + 8][kk + t2 + 8];
#pragma unroll
            for (int nt = 0; nt < 8; nt++) {
                uint32_t b0 = *(const uint32_t*)&Bs[nt * 8 + g][kk + t2];
                uint32_t b1f = *(const uint32_t*)&Bs[nt * 8 + g][kk + t2 + 8];
                asm volatile(
                    "mma.sync.aligned.m16n8k16.row.col.f32.f16.f16.f32 "
                    "{%0,%1,%2,%3}, {%4,%5,%6,%7}, {%8,%9}, {%0,%1,%2,%3};"
                    : "+f"(acc[nt][0]), "+f"(acc[nt][1]),
                      "+f"(acc[nt][2]), "+f"(acc[nt][3])
                    : "r"(a0), "r"(a1), "r"(a2), "r"(a3), "r"(b0), "r"(b1f));
            }
        }
        __syncthreads();
    }

    int r1 = row0 + 16 * warp + g;
    int r2 = r1 + 8;
    float dv1 = (r1 < NN) ? g_dinv[r1] : 0.f;
    float dv2 = (r2 < NN) ? g_dinv[r2] : 0.f;
#pragma unroll
    for (int nt = 0; nt < 8; nt++) {
        int c0 = nt * 8 + t2;
        float bb0 = bsh[c0], bb1 = bsh[c0 + 1];
        if (r1 < NN) {
            float h0 = fmaxf(acc[nt][0] + bb0, 0.f);
            float h1 = fmaxf(acc[nt][1] + bb1, 0.f);
            g_H[0][r1 * 32 + (c0 >> 1)] = __floats2half2_rn(dv1 * h0, dv1 * h1);
        }
        if (r2 < NN) {
            float h0 = fmaxf(acc[nt][2] + bb0, 0.f);
            float h1 = fmaxf(acc[nt][3] + bb1, 0.f);
            g_H[0][r2 * 32 + (c0 >> 1)] = __floats2half2_rn(dv2 * h0, dv2 * h1);
        }
    }
}

// ======================= Jacobi propagation (hot loop) ===================
// Warp per node (sequential order), half2 per lane (128B/row). Padded CSR:
// tail-free 8-unrolled gather with software-pipelined int4 index loads.
// Gather body is the R11 measured local optimum — do not add registers.
// 256-thread blocks: same warps/SM, half the CTAs -> less L1tex-queue spread.

__device__ __forceinline__ void gather8(const __half2* __restrict__ g,
                                        const int* __restrict__ src,
                                        int s, int e, int lane,
                                        float& gx, float& gy) {
    float a0x = 0.f, a0y = 0.f, a1x = 0.f, a1y = 0.f;
    float a2x = 0.f, a2y = 0.f, a3x = 0.f, a3y = 0.f;
    int4 ia = *(const int4*)(src + s);
    int4 ib = *(const int4*)(src + s + 4);
    for (int j = s; j < e; j += 8) {
        // prefetch next iteration's indices (safe over-read: capacity slack)
        int4 na = *(const int4*)(src + j + 8);
        int4 nb = *(const int4*)(src + j + 12);
        float2 v0 = __half22float2(g[ia.x * 32 + lane]);
        float2 v1 = __half22float2(g[ia.y * 32 + lane]);
        float2 v2 = __half22float2(g[ia.z * 32 + lane]);
        float2 v3 = __half22float2(g[ia.w * 32 + lane]);
        float2 v4 = __half22float2(g[ib.x * 32 + lane]);
        float2 v5 = __half22float2(g[ib.y * 32 + lane]);
        float2 v6 = __half22float2(g[ib.z * 32 + lane]);
        float2 v7 = __half22float2(g[ib.w * 32 + lane]);
        a0x += v0.x + v4.x; a0y += v0.y + v4.y;
        a1x += v1.x + v5.x; a1y += v1.y + v5.y;
        a2x += v2.x + v6.x; a2y += v2.y + v6.y;
        a3x += v3.x + v7.x; a3y += v3.y + v7.y;
        ia = na; ib = nb;
    }
    gx = (a0x + a1x) + (a2x + a3x);
    gy = (a0y + a1y) + (a2y + a3y);
}

__global__ __launch_bounds__(PROP_TPB) void prop_first_kernel() {
    int w = threadIdx.x >> 5, lane = threadIdx.x & 31;
    int node = blockIdx.x * (PROP_TPB / 32) + w;
    if (node >= NN) return;
    const __half2* __restrict__ g = g_H[0];
    __half2* __restrict__ go = g_H[1];

    int idx2 = node * 32 + lane;
    float2 self = __half22float2(g[idx2]);
    float gx, gy;
    gather8(g, g_src, g_off[node], g_off[node + 1], lane, gx, gy);
    gx += self.x; gy += self.y;                // self loop
    float dv = g_dinv[node];
    float dv2f = dv * dv;
    go[idx2] = __floats2half2_rn(dv2f * gx, dv2f * gy);
}

__global__ __launch_bounds__(PROP_TPB) void prop_step_kernel(float An, float Bn, float Cn,
                                                             int kin, int kt0, int kout) {
    int w = threadIdx.x >> 5, lane = threadIdx.x & 31;
    int node = blockIdx.x * (PROP_TPB / 32) + w;
    if (node >= NN) return;
    const __half2* __restrict__ g = g_H[kin];
    const __half2* __restrict__ gt0 = g_H[kt0];
    __half2* __restrict__ go = g_H[kout];

    int idx2 = node * 32 + lane;
    float2 self = __half22float2(g[idx2]);     // dinv * t1
    float2 g0 = __half22float2(__ldcs(&gt0[idx2]));  // dinv * t0 (evict-first;
                                               // not re-read before overwrite)
    float gx, gy;
    gather8(g, g_src, g_off[node], g_off[node + 1], lane, gx, gy);
    gx += self.x; gy += self.y;                // self loop

    float dv = g_dinv[node], ds = g_ds[node];
    float px = dv * gx, py = dv * gy;          // (P t1)
    float t1x = self.x * ds, t1y = self.y * ds;
    float t0x = g0.x * ds, t0y = g0.y * ds;
    float t2x = An * px + Bn * t1x - Cn * t0x;
    float t2y = An * py + Bn * t1y - Cn * t0y;
    go[idx2] = __floats2half2_rn(dv * t2x, dv * t2y);
}

// ======================= layer epilogue (vectorized) =====================
// slot0' = relu(sum_k c_k slot_k).  Thread handles 4 half2 = 8 channels.
__global__ void layer_epi_kernel(const float* __restrict__ coeffs, int base) {
    int i = blockIdx.x * 256 + threadIdx.x;     // int4 item: node=i>>3, 8 ch
    if (i >= NN * 8) return;
    float c[KORD + 1];
#pragma unroll
    for (int k = 0; k <= KORD; k++) c[k] = coeffs[base + k];
    int off = i * 4;                            // half2 offset (16B aligned)
    float ax[4] = {0.f, 0.f, 0.f, 0.f};
    float ay[4] = {0.f, 0.f, 0.f, 0.f};
#pragma unroll
    for (int k = 0; k <= KORD; k++) {
        int4 raw = *(const int4*)&g_H[k][off];
        const __half2* h = (const __half2*)&raw;
#pragma unroll
        for (int q = 0; q < 4; q++) {
            float2 v = __half22float2(h[q]);
            ax[q] += c[k] * v.x;
            ay[q] += c[k] * v.y;
        }
    }
    int4 outw;
    __half2* ho = (__half2*)&outw;
#pragma unroll
    for (int q = 0; q < 4; q++)
        ho[q] = __floats2half2_rn(fmaxf(ax[q], 0.f), fmaxf(ay[q], 0.f));
    *(int4*)&g_H[0][off] = outw;
}

// ============== fused layer-2 epilogue + GEMM2 ===========================
// xs[r][:] = ds * relu(sum_k c_k slot_k) ; out = xs @ W2 + b2
__global__ __launch_bounds__(256) void epi_gemm2_kernel(const float* __restrict__ coeffs,
                                                        int base,
                                                        const float* __restrict__ W2,
                                                        const float* __restrict__ b2,
                                                        float* __restrict__ out) {
    __shared__ __align__(16) float ws[64][32];
    __shared__ __align__(16) float xs[32][65];
    int tid = threadIdx.x;
    int row0 = blockIdx.x * 32;

    // W2 into smem
    for (int l = tid; l < 64 * 32; l += 256) ws[l >> 5][l & 31] = W2[l];

    // epilogue: 32 nodes x 8 items (4 half2 each); thread tid = one item
    {
        float c[KORD + 1];
#pragma unroll
        for (int k = 0; k <= KORD; k++) c[k] = coeffs[base + k];
        int r = tid >> 3;                   // 0..31
        int kk0 = (tid & 7) * 4;            // half2 offset within row
        int gr = row0 + r;
        int off = gr * 32 + kk0;
        float ax[4] = {0.f, 0.f, 0.f, 0.f};
        float ay[4] = {0.f, 0.f, 0.f, 0.f};
#pragma unroll
        for (int k = 0; k <= KORD; k++) {
            int4 raw = *(const int4*)&g_H[k][off];
            const __half2* h = (const __half2*)&raw;
#pragma unroll
            for (int q = 0; q < 4; q++) {
                float2 v = __half22float2(h[q]);
                ax[q] += c[k] * v.x;
                ay[q] += c[k] * v.y;
            }
        }
        float dsv = g_ds[gr];
#pragma unroll
        for (int q = 0; q < 4; q++) {
            xs[r][(kk0 + q) * 2]     = dsv * fmaxf(ax[q], 0.f);
            xs[r][(kk0 + q) * 2 + 1] = dsv * fmaxf(ay[q], 0.f);
        }
    }
    __syncthreads();

    int tx = tid & 31;
    int ty = tid >> 5;
    float acc[4] = {0.f, 0.f, 0.f, 0.f};
#pragma unroll
    for (int k = 0; k < 64; k++) {
        float wv = ws[k][tx];
#pragma unroll
        for (int i = 0; i < 4; i++) acc[i] += xs[ty * 4 + i][k] * wv;
    }
    float bb = b2[tx];
#pragma unroll
    for (int i = 0; i < 4; i++) {
        int gr = row0 + ty * 4 + i;
        out[gr * OUTC + tx] = acc[i] + bb;
    }
}

// ======================= launcher =======================

extern "C" void kernel_launch(void* const* d_in, const int* in_sizes, int n_in,
                              void* d_out, int out_size) {
    const float* x      = (const float*)d_in[0];
    const void*  ei     = d_in[1];
    const float* W1     = (const float*)d_in[2];
    const float* b1     = (const float*)d_in[3];
    const float* coeffs = (const float*)d_in[4];
    const float* W2     = (const float*)d_in[5];
    const float* b2     = (const float*)d_in[6];
    float*       out    = (float*)d_out;

    zero_detect_kernel<<<(NEP_MAX / 4 + 255) / 256, 256>>>((const int*)ei);
    count_deg_kernel<<<(NE / 4 + 255) / 256, 256>>>(ei);
    scan1_kernel<<<NBLK_SCAN, 256>>>();
    scan23_kernel<<<(NN + 511) / 512, 512>>>();
    scatter_kernel<<<(NE / 4 + 255) / 256, 256>>>(ei);

    gemm1_kernel<<<(NN + 63) / 64, 128>>>(x, W1, b1);

    const double a = 0.5, b = 0.5;
    for (int l = 0; l < NLAYERS; l++) {
        prop_first_kernel<<<NBLK_PROP, PROP_TPB>>>();
        for (int k = 2; k <= KORD; k++) {
            double n = (double)(k - 1);
            double An = (2 * n + a + b + 1) * (2 * n + a + b + 2)
                        / (2 * (n + 1) * (n + a + b + 1));
            double Bn = (a * a - b * b) * (2 * n + a + b + 1)
                        / (2 * (n + 1) * (n + a + b + 1) * (2 * n + a + b));
            double Cn = (n + a) * (n + b) * (2 * n + a + b + 2)
                        / ((n + 1) * (n + a + b + 1) * (2 * n + a + b));
            prop_step_kernel<<<NBLK_PROP, PROP_TPB>>>((float)An, (float)Bn, (float)Cn,
                                                      k - 1, k - 2, k);
        }
        if (l == 0)
            layer_epi_kernel<<<(NN * 8 + 255) / 256, 256>>>(coeffs, 0);
        else
            epi_gemm2_kernel<<<NN / 32, 256>>>(coeffs, KORD + 1, W2, b2, out);
    }
}

// round 15
// speedup vs baseline: 1.0404x; 1.0404x over previous
#include <cuda_runtime.h>
#include <cuda_fp16.h>
#include <cstdint>
#include <math.h>

// ---------------- problem constants (fixed by reference) ----------------
#define NN      100000      // N_NODES
#define NE      1600000     // N_EDGES
#define HID     64
#define INC     256
#define OUTC    32
#define KORD    10
#define NLAYERS 2
#define NBLK_SCAN 391       // ceil(NN/256)
#define NBLK_PROP 25000     // ceil(NN/4), 4 nodes (warps) per block — R13 optimum
#define NEP_MAX (NE + 8 * NN)   // padded CSR capacity (2.4M)

// ---------------- device scratch (static globals: allowed) --------------
__device__ int   g_is64;
__device__ int   g_deg[NN];
__device__ float g_dinv[NN];        // 1/sqrt(deg+1)
__device__ float g_ds[NN];          // sqrt(deg+1)
__device__ int   g_off[NN + 1];     // padded-CSR offsets (multiples of 8)
__device__ int   g_cur[NN];
__device__ __align__(16) int g_src[NEP_MAX];
__device__ int   g_bsum[512];

// slot k holds dinv * t_k as half2 (32 half2 = 64 ch per node).
// Row NN is the zero sentinel row for CSR padding — never written.
__device__ __align__(16) __half2 g_H[KORD + 1][(NN + 8) * 32];

// ============== dtype detect + zero deg + src sentinel fill (fused) =====
__global__ void zero_detect_kernel(const int* __restrict__ ei32) {
    int i = blockIdx.x * 256 + threadIdx.x;
    if (i < NN) g_deg[i] = 0;
    if (i < NEP_MAX / 4)
        *(int4*)&g_src[i * 4] = make_int4(NN, NN, NN, NN);
    if (blockIdx.x == 0) {
        __shared__ int nz;
        if (threadIdx.x == 0) nz = 0;
        __syncthreads();
        for (int t = threadIdx.x; t < 4096; t += 256)
            if (ei32[2 * t + 1] != 0) nz = 1;
        __syncthreads();
        if (threadIdx.x == 0) g_is64 = nz ? 0 : 1;
    }
}

// ======================= CSR build (vectorized, 4 edges/thread) =========

__device__ __forceinline__ int4 edge4_at(const void* __restrict__ ei, int base, int is64) {
    if (is64) {
        const longlong2* p = (const longlong2*)((const long long*)ei + base);
        longlong2 a = p[0], b = p[1];
        return make_int4((int)a.x, (int)a.y, (int)b.x, (int)b.y);
    }
    return *(const int4*)((const int*)ei + base);
}

__global__ void count_deg_kernel(const void* __restrict__ ei) {
    int is64 = g_is64;
    int e4 = blockIdx.x * 256 + threadIdx.x;
    if (e4 < NE / 4) {
        int4 c = edge4_at(ei, NE + e4 * 4, is64);
        atomicAdd(&g_deg[c.x], 1);
        atomicAdd(&g_deg[c.y], 1);
        atomicAdd(&g_deg[c.z], 1);
        atomicAdd(&g_deg[c.w], 1);
    }
}

// scan of PADDED degrees (rounded up to multiple of 8); dinv/ds from real deg
__global__ void scan1_kernel() {
    __shared__ int sh[256];
    int tid = threadIdx.x;
    int i = blockIdx.x * 256 + tid;
    int v = (i < NN) ? g_deg[i] : 0;
    if (i < NN) {
        float d = (float)(v + 1);
        g_dinv[i] = rsqrtf(d);
        g_ds[i]   = sqrtf(d);
    }
    int pv = (v + 7) & ~7;                   // padded degree
    sh[tid] = pv;
    __syncthreads();
#pragma unroll
    for (int o = 1; o < 256; o <<= 1) {
        int t = (tid >= o) ? sh[tid - o] : 0;
        __syncthreads();
        sh[tid] += t;
        __syncthreads();
    }
    if (i < NN) g_off[i] = sh[tid] - pv;
    if (tid == 255) g_bsum[blockIdx.x] = sh[255];
}

__global__ void scan23_kernel() {
    __shared__ int sh[512];
    int tid = threadIdx.x;
    int v = (tid < NBLK_SCAN) ? g_bsum[tid] : 0;
    sh[tid] = v;
    __syncthreads();
#pragma unroll
    for (int o = 1; o < 512; o <<= 1) {
        int t = (tid >= o) ? sh[tid - o] : 0;
        __syncthreads();
        sh[tid] += t;
        __syncthreads();
    }
    int i = blockIdx.x * 512 + tid;
    if (i < NN) {
        int sb = i >> 8;
        int add = (sb > 0) ? sh[sb - 1] : 0;
        int o = g_off[i] + add;
        g_off[i] = o;
        g_cur[i] = o;
    }
    if (blockIdx.x == 0 && tid == 0) g_off[NN] = sh[NBLK_SCAN - 1];  // total padded
}

__global__ void scatter_kernel(const void* __restrict__ ei) {
    int is64 = g_is64;
    int e4 = blockIdx.x * 256 + threadIdx.x;
    if (e4 < NE / 4) {
        int4 r = edge4_at(ei, e4 * 4, is64);
        int4 c = edge4_at(ei, NE + e4 * 4, is64);
        g_src[atomicAdd(&g_cur[c.x], 1)] = r.x;
        g_src[atomicAdd(&g_cur[c.y], 1)] = r.y;
        g_src[atomicAdd(&g_cur[c.z], 1)] = r.z;
        g_src[atomicAdd(&g_cur[c.w], 1)] = r.w;
    }
}

// ======================= GEMM1 (tensor cores, fp16 in / fp32 acc) ========
// g_H[0] = half(dinv * relu(x @ W1 + b1)).  KC=32 (R11 form).
// Runs on a second stream, overlapped with scan23+scatter (independent).

#define KC 32

__global__ __launch_bounds__(128) void gemm1_kernel(const float* __restrict__ x,
                                                    const float* __restrict__ W1,
                                                    const float* __restrict__ b1) {
    __shared__ __align__(16) __half As[64][KC + 8];
    __shared__ __align__(16) __half Bs[64][KC + 8];
    __shared__ float bsh[64];
    int tid = threadIdx.x;
    int warp = tid >> 5, lane = tid & 31;
    int g = lane >> 2;
    int t2 = (lane & 3) * 2;
    int row0 = blockIdx.x * 64;

    if (tid < 64) bsh[tid] = b1[tid];

    float acc[8][4];
#pragma unroll
    for (int nt = 0; nt < 8; nt++)
#pragma unroll
        for (int q = 0; q < 4; q++) acc[nt][q] = 0.f;

    for (int kc = 0; kc < INC; kc += KC) {
        {
            int r = tid >> 1;
            int kp = (tid & 1) * 16;
            int gr = row0 + r;
            const float4* xr = (const float4*)(x + (long long)gr * INC + kc + kp);
            float4 v[4];
#pragma unroll
            for (int q = 0; q < 4; q++)
                v[q] = (gr < NN) ? xr[q] : make_float4(0.f, 0.f, 0.f, 0.f);
            __half2* dst = (__half2*)&As[r][kp];
#pragma unroll
            for (int q = 0; q < 4; q++) {
                dst[q * 2 + 0] = __floats2half2_rn(v[q].x, v[q].y);
                dst[q * 2 + 1] = __floats2half2_rn(v[q].z, v[q].w);
            }
        }
        for (int q = 0; q < 4; q++) {
            int idx = tid + 128 * q;
            int k = idx >> 4;
            int n0 = (idx & 15) * 4;
            float4 wv = *(const float4*)(W1 + (long long)(kc + k) * HID + n0);
            Bs[n0 + 0][k] = __float2half_rn(wv.x);
            Bs[n0 + 1][k] = __float2half_rn(wv.y);
            Bs[n0 + 2][k] = __float2half_rn(wv.z);
            Bs[n0 + 3][k] = __float2half_rn(wv.w);
        }
        __syncthreads();

#pragma unroll
        for (int kk = 0; kk < KC; kk += 16) {
            uint32_t a0 = *(const uint32_t*)&As[16 * warp + g    ][kk + t2];
            uint32_t a1 = *(const uint32_t*)&As[16 * warp + g + 8][kk + t2];
            uint32_t a2 = *(const uint32_t*)&As[16 * warp + g    ][kk + t2 + 8];
            uint32_t a3 = *(const uint32_t*)&As[16 * warp + g + 8][kk + t2 + 8];
#pragma unroll
            for (int nt = 0; nt < 8; nt++) {
                uint32_t b0 = *(const uint32_t*)&Bs[nt * 8 + g][kk + t2];
                uint32_t b1f = *(const uint32_t*)&Bs[nt * 8 + g][kk + t2 + 8];
                asm volatile(
                    "mma.sync.aligned.m16n8k16.row.col.f32.f16.f16.f32 "
                    "{%0,%1,%2,%3}, {%4,%5,%6,%7}, {%8,%9}, {%0,%1,%2,%3};"
                    : "+f"(acc[nt][0]), "+f"(acc[nt][1]),
                      "+f"(acc[nt][2]), "+f"(acc[nt][3])
                    : "r"(a0), "r"(a1), "r"(a2), "r"(a3), "r"(b0), "r"(b1f));
            }
        }
        __syncthreads();
    }

    int r1 = row0 + 16 * warp + g;
    int r2 = r1 + 8;
    float dv1 = (r1 < NN) ? g_dinv[r1] : 0.f;
    float dv2 = (r2 < NN) ? g_dinv[r2] : 0.f;
#pragma unroll
    for (int nt = 0; nt < 8; nt++) {
        int c0 = nt * 8 + t2;
        float bb0 = bsh[c0], bb1 = bsh[c0 + 1];
        if (r1 < NN) {
            float h0 = fmaxf(acc[nt][0] + bb0, 0.f);
            float h1 = fmaxf(acc[nt][1] + bb1, 0.f);
            g_H[0][r1 * 32 + (c0 >> 1)] = __floats2half2_rn(dv1 * h0, dv1 * h1);
        }
        if (r2 < NN) {
            float h0 = fmaxf(acc[nt][2] + bb0, 0.f);
            float h1 = fmaxf(acc[nt][3] + bb1, 0.f);
            g_H[0][r2 * 32 + (c0 >> 1)] = __floats2half2_rn(dv2 * h0, dv2 * h1);
        }
    }
}

// ======================= Jacobi propagation (hot loop) ===================
// EXACT R13/R11 form — measured local optimum (MLP depth, block shape,
// permutation, value pipelining, cache hints all regress it).

__device__ __forceinline__ void gather8(const __half2* __restrict__ g,
                                        const int* __restrict__ src,
                                        int s, int e, int lane,
                                        float& gx, float& gy) {
    float a0x = 0.f, a0y = 0.f, a1x = 0.f, a1y = 0.f;
    float a2x = 0.f, a2y = 0.f, a3x = 0.f, a3y = 0.f;
    int4 ia = *(const int4*)(src + s);
    int4 ib = *(const int4*)(src + s + 4);
    for (int j = s; j < e; j += 8) {
        // prefetch next iteration's indices (safe over-read: capacity slack)
        int4 na = *(const int4*)(src + j + 8);
        int4 nb = *(const int4*)(src + j + 12);
        float2 v0 = __half22float2(g[ia.x * 32 + lane]);
        float2 v1 = __half22float2(g[ia.y * 32 + lane]);
        float2 v2 = __half22float2(g[ia.z * 32 + lane]);
        float2 v3 = __half22float2(g[ia.w * 32 + lane]);
        float2 v4 = __half22float2(g[ib.x * 32 + lane]);
        float2 v5 = __half22float2(g[ib.y * 32 + lane]);
        float2 v6 = __half22float2(g[ib.z * 32 + lane]);
        float2 v7 = __half22float2(g[ib.w * 32 + lane]);
        a0x += v0.x + v4.x; a0y += v0.y + v4.y;
        a1x += v1.x + v5.x; a1y += v1.y + v5.y;
        a2x += v2.x + v6.x; a2y += v2.y + v6.y;
        a3x += v3.x + v7.x; a3y += v3.y + v7.y;
        ia = na; ib = nb;
    }
    gx = (a0x + a1x) + (a2x + a3x);
    gy = (a0y + a1y) + (a2y + a3y);
}

__global__ __launch_bounds__(128) void prop_first_kernel() {
    int w = threadIdx.x >> 5, lane = threadIdx.x & 31;
    int node = blockIdx.x * 4 + w;
    if (node >= NN) return;
    const __half2* __restrict__ g = g_H[0];
    __half2* __restrict__ go = g_H[1];

    int idx2 = node * 32 + lane;
    float2 self = __half22float2(g[idx2]);
    float gx, gy;
    gather8(g, g_src, g_off[node], g_off[node + 1], lane, gx, gy);
    gx += self.x; gy += self.y;                // self loop
    float dv = g_dinv[node];
    float dv2f = dv * dv;
    go[idx2] = __floats2half2_rn(dv2f * gx, dv2f * gy);
}

__global__ __launch_bounds__(128) void prop_step_kernel(float An, float Bn, float Cn,
                                                        int kin, int kt0, int kout) {
    int w = threadIdx.x >> 5, lane = threadIdx.x & 31;
    int node = blockIdx.x * 4 + w;
    if (node >= NN) return;
    const __half2* __restrict__ g = g_H[kin];
    const __half2* __restrict__ gt0 = g_H[kt0];
    __half2* __restrict__ go = g_H[kout];

    int idx2 = node * 32 + lane;
    float2 self = __half22float2(g[idx2]);     // dinv * t1
    float2 g0 = __half22float2(__ldcs(&gt0[idx2]));  // dinv * t0 (evict-first;
                                               // not re-read before overwrite)
    float gx, gy;
    gather8(g, g_src, g_off[node], g_off[node + 1], lane, gx, gy);
    gx += self.x; gy += self.y;                // self loop

    float dv = g_dinv[node], ds = g_ds[node];
    float px = dv * gx, py = dv * gy;          // (P t1)
    float t1x = self.x * ds, t1y = self.y * ds;
    float t0x = g0.x * ds, t0y = g0.y * ds;
    float t2x = An * px + Bn * t1x - Cn * t0x;
    float t2y = An * py + Bn * t1y - Cn * t0y;
    go[idx2] = __floats2half2_rn(dv * t2x, dv * t2y);
}

// ======================= layer epilogue (vectorized) =====================
// slot0' = relu(sum_k c_k slot_k).  Thread handles 4 half2 = 8 channels.
__global__ void layer_epi_kernel(const float* __restrict__ coeffs, int base) {
    int i = blockIdx.x * 256 + threadIdx.x;     // int4 item: node=i>>3, 8 ch
    if (i >= NN * 8) return;
    float c[KORD + 1];
#pragma unroll
    for (int k = 0; k <= KORD; k++) c[k] = coeffs[base + k];
    int off = i * 4;                            // half2 offset (16B aligned)
    float ax[4] = {0.f, 0.f, 0.f, 0.f};
    float ay[4] = {0.f, 0.f, 0.f, 0.f};
#pragma unroll
    for (int k = 0; k <= KORD; k++) {
        int4 raw = *(const int4*)&g_H[k][off];
        const __half2* h = (const __half2*)&raw;
#pragma unroll
        for (int q = 0; q < 4; q++) {
            float2 v = __half22float2(h[q]);
            ax[q] += c[k] * v.x;
            ay[q] += c[k] * v.y;
        }
    }
    int4 outw;
    __half2* ho = (__half2*)&outw;
#pragma unroll
    for (int q = 0; q < 4; q++)
        ho[q] = __floats2half2_rn(fmaxf(ax[q], 0.f), fmaxf(ay[q], 0.f));
    *(int4*)&g_H[0][off] = outw;
}

// ============== fused layer-2 epilogue + GEMM2 ===========================
__global__ __launch_bounds__(256) void epi_gemm2_kernel(const float* __restrict__ coeffs,
                                                        int base,
                                                        const float* __restrict__ W2,
                                                        const float* __restrict__ b2,
                                                        float* __restrict__ out) {
    __shared__ __align__(16) float ws[64][32];
    __shared__ __align__(16) float xs[32][65];
    int tid = threadIdx.x;
    int row0 = blockIdx.x * 32;

    for (int l = tid; l < 64 * 32; l += 256) ws[l >> 5][l & 31] = W2[l];

    {
        float c[KORD + 1];
#pragma unroll
        for (int k = 0; k <= KORD; k++) c[k] = coeffs[base + k];
        int r = tid >> 3;
        int kk0 = (tid & 7) * 4;
        int gr = row0 + r;
        int off = gr * 32 + kk0;
        float ax[4] = {0.f, 0.f, 0.f, 0.f};
        float ay[4] = {0.f, 0.f, 0.f, 0.f};
#pragma unroll
        for (int k = 0; k <= KORD; k++) {
            int4 raw = *(const int4*)&g_H[k][off];
            const __half2* h = (const __half2*)&raw;
#pragma unroll
            for (int q = 0; q < 4; q++) {
                float2 v = __half22float2(h[q]);
                ax[q] += c[k] * v.x;
                ay[q] += c[k] * v.y;
            }
        }
        float dsv = g_ds[gr];
#pragma unroll
        for (int q = 0; q < 4; q++) {
            xs[r][(kk0 + q) * 2]     = dsv * fmaxf(ax[q], 0.f);
            xs[r][(kk0 + q) * 2 + 1] = dsv * fmaxf(ay[q], 0.f);
        }
    }
    __syncthreads();

    int tx = tid & 31;
    int ty = tid >> 5;
    float acc[4] = {0.f, 0.f, 0.f, 0.f};
#pragma unroll
    for (int k = 0; k < 64; k++) {
        float wv = ws[k][tx];
#pragma unroll
        for (int i = 0; i < 4; i++) acc[i] += xs[ty * 4 + i][k] * wv;
    }
    float bb = b2[tx];
#pragma unroll
    for (int i = 0; i < 4; i++) {
        int gr = row0 + ty * 4 + i;
        out[gr * OUTC + tx] = acc[i] + bb;
    }
}

// ======================= launcher =======================

extern "C" void kernel_launch(void* const* d_in, const int* in_sizes, int n_in,
                              void* d_out, int out_size) {
    const float* x      = (const float*)d_in[0];
    const void*  ei     = d_in[1];
    const float* W1     = (const float*)d_in[2];
    const float* b1     = (const float*)d_in[3];
    const float* coeffs = (const float*)d_in[4];
    const float* W2     = (const float*)d_in[5];
    const float* b2     = (const float*)d_in[6];
    float*       out    = (float*)d_out;

    // one-time host resources (no device memory; device work stays identical)
    static cudaStream_t s2 = nullptr;
    static cudaEvent_t evFork = nullptr, evJoin = nullptr;
    if (s2 == nullptr) {
        cudaStreamCreateWithFlags(&s2, cudaStreamNonBlocking);
        cudaEventCreateWithFlags(&evFork, cudaEventDisableTiming);
        cudaEventCreateWithFlags(&evJoin, cudaEventDisableTiming);
    }

    zero_detect_kernel<<<(NEP_MAX / 4 + 255) / 256, 256>>>((const int*)ei);
    count_deg_kernel<<<(NE / 4 + 255) / 256, 256>>>(ei);
    scan1_kernel<<<NBLK_SCAN, 256>>>();

    // fork: gemm1 (needs only dinv) runs on s2, overlapped with scan23+scatter
    cudaEventRecord(evFork, 0);
    cudaStreamWaitEvent(s2, evFork, 0);
    gemm1_kernel<<<(NN + 63) / 64, 128, 0, s2>>>(x, W1, b1);
    cudaEventRecord(evJoin, s2);

    scan23_kernel<<<(NN + 511) / 512, 512>>>();
    scatter_kernel<<<(NE / 4 + 255) / 256, 256>>>(ei);

    // join: props need both CSR (default stream) and g_H[0] (s2)
    cudaStreamWaitEvent(0, evJoin, 0);

    const double a = 0.5, b = 0.5;
    for (int l = 0; l < NLAYERS; l++) {
        prop_first_kernel<<<NBLK_PROP, 128>>>();
        for (int k = 2; k <= KORD; k++) {
            double n = (double)(k - 1);
            double An = (2 * n + a + b + 1) * (2 * n + a + b + 2)
                        / (2 * (n + 1) * (n + a + b + 1));
            double Bn = (a * a - b * b) * (2 * n + a + b + 1)
                        / (2 * (n + 1) * (n + a + b + 1) * (2 * n + a + b));
            double Cn = (n + a) * (n + b) * (2 * n + a + b + 2)
                        / ((n + 1) * (n + a + b + 1) * (2 * n + a + b));
            prop_step_kernel<<<NBLK_PROP, 128>>>((float)An, (float)Bn, (float)Cn,
                                                 k - 1, k - 2, k);
        }
        if (l == 0)
            layer_epi_kernel<<<(NN * 8 + 255) / 256, 256>>>(coeffs, 0);
        else
            epi_gemm2_kernel<<<NN / 32, 256>>>(coeffs, KORD + 1, W2, b2, out);
    }
}

// round 17
// speedup vs baseline: 1.0625x; 1.0213x over previous
#include <cuda_runtime.h>
#include <cuda_fp16.h>
#include <cstdint>
#include <math.h>

// ---------------- problem constants (fixed by reference) ----------------
#define NN      100000      // N_NODES
#define NE      1600000     // N_EDGES
#define HID     64
#define INC     256
#define OUTC    32
#define KORD    10
#define NLAYERS 2
#define NBLK_SCAN 391       // ceil(NN/256)
#define NBLK_PROP 25000     // ceil(NN/4), 4 nodes (warps) per block — R13 optimum
#define NEP_MAX (NE + 8 * NN)   // padded CSR capacity (2.4M)

// ---------------- device scratch (static globals: allowed) --------------
__device__ int   g_is64;
__device__ int   g_deg[NN];
__device__ float g_dinv[NN];        // 1/sqrt(deg+1)
__device__ float g_ds[NN];          // sqrt(deg+1)
__device__ int   g_off[NN + 1];     // padded-CSR offsets (multiples of 8)
__device__ int   g_cur[NN];
__device__ __align__(16) int g_src[NEP_MAX];
__device__ int   g_bsum[512];

// slot k holds dinv * t_k as half2 (32 half2 = 64 ch per node).
// Row NN is the zero sentinel row for CSR padding — never written.
__device__ __align__(16) __half2 g_H[KORD + 1][(NN + 8) * 32];

__device__ __forceinline__ uint32_t smem_u32(const void* p) {
    return (uint32_t)__cvta_generic_to_shared(p);
}
__device__ __forceinline__ uint32_t h2_bits(__half2 h) {
    return *(uint32_t*)&h;
}

// ============== dtype detect + zero deg + src sentinel fill (fused) =====
__global__ void zero_detect_kernel(const int* __restrict__ ei32) {
    int i = blockIdx.x * 256 + threadIdx.x;
    if (i < NN) g_deg[i] = 0;
    if (i < NEP_MAX / 4)
        *(int4*)&g_src[i * 4] = make_int4(NN, NN, NN, NN);
    if (blockIdx.x == 0) {
        __shared__ int nz;
        if (threadIdx.x == 0) nz = 0;
        __syncthreads();
        for (int t = threadIdx.x; t < 4096; t += 256)
            if (ei32[2 * t + 1] != 0) nz = 1;
        __syncthreads();
        if (threadIdx.x == 0) g_is64 = nz ? 0 : 1;
    }
}

// ======================= CSR build (vectorized, 4 edges/thread) =========

__device__ __forceinline__ int4 edge4_at(const void* __restrict__ ei, int base, int is64) {
    if (is64) {
        const longlong2* p = (const longlong2*)((const long long*)ei + base);
        longlong2 a = p[0], b = p[1];
        return make_int4((int)a.x, (int)a.y, (int)b.x, (int)b.y);
    }
    return *(const int4*)((const int*)ei + base);
}

__global__ void count_deg_kernel(const void* __restrict__ ei) {
    int is64 = g_is64;
    int e4 = blockIdx.x * 256 + threadIdx.x;
    if (e4 < NE / 4) {
        int4 c = edge4_at(ei, NE + e4 * 4, is64);
        atomicAdd(&g_deg[c.x], 1);
        atomicAdd(&g_deg[c.y], 1);
        atomicAdd(&g_deg[c.z], 1);
        atomicAdd(&g_deg[c.w], 1);
    }
}

// scan of PADDED degrees (rounded up to multiple of 8); dinv/ds from real deg
__global__ void scan1_kernel() {
    __shared__ int sh[256];
    int tid = threadIdx.x;
    int i = blockIdx.x * 256 + tid;
    int v = (i < NN) ? g_deg[i] : 0;
    if (i < NN) {
        float d = (float)(v + 1);
        g_dinv[i] = rsqrtf(d);
        g_ds[i]   = sqrtf(d);
    }
    int pv = (v + 7) & ~7;                   // padded degree
    sh[tid] = pv;
    __syncthreads();
#pragma unroll
    for (int o = 1; o < 256; o <<= 1) {
        int t = (tid >= o) ? sh[tid - o] : 0;
        __syncthreads();
        sh[tid] += t;
        __syncthreads();
    }
    if (i < NN) g_off[i] = sh[tid] - pv;
    if (tid == 255) g_bsum[blockIdx.x] = sh[255];
}

__global__ void scan23_kernel() {
    __shared__ int sh[512];
    int tid = threadIdx.x;
    int v = (tid < NBLK_SCAN) ? g_bsum[tid] : 0;
    sh[tid] = v;
    __syncthreads();
#pragma unroll
    for (int o = 1; o < 512; o <<= 1) {
        int t = (tid >= o) ? sh[tid - o] : 0;
        __syncthreads();
        sh[tid] += t;
        __syncthreads();
    }
    int i = blockIdx.x * 512 + tid;
    if (i < NN) {
        int sb = i >> 8;
        int add = (sb > 0) ? sh[sb - 1] : 0;
        int o = g_off[i] + add;
        g_off[i] = o;
        g_cur[i] = o;
    }
    if (blockIdx.x == 0 && tid == 0) g_off[NN] = sh[NBLK_SCAN - 1];  // total padded
}

__global__ void scatter_kernel(const void* __restrict__ ei) {
    int is64 = g_is64;
    int e4 = blockIdx.x * 256 + threadIdx.x;
    if (e4 < NE / 4) {
        int4 r = edge4_at(ei, e4 * 4, is64);
        int4 c = edge4_at(ei, NE + e4 * 4, is64);
        g_src[atomicAdd(&g_cur[c.x], 1)] = r.x;
        g_src[atomicAdd(&g_cur[c.y], 1)] = r.y;
        g_src[atomicAdd(&g_cur[c.z], 1)] = r.z;
        g_src[atomicAdd(&g_cur[c.w], 1)] = r.w;
    }
}

// ======================= GEMM1 (tensor cores + ldmatrix) =================
// g_H[0] = half(dinv * relu(x @ W1 + b1)).  KC=32.
// L1-op diet vs R15 (74.6% L1-bound): W1 stored untransposed (vector st.64),
// transpose via ldmatrix.x4.trans; A fragments via ldmatrix.x4. x loads via
// __ldcs (x is read exactly once ever — streaming hint valid here).
// Runs on a second stream, overlapped with scan23+scatter.

#define KC 32

__global__ __launch_bounds__(128) void gemm1_kernel(const float* __restrict__ x,
                                                    const float* __restrict__ W1,
                                                    const float* __restrict__ b1) {
    __shared__ __align__(16) __half As[64][KC + 8];    // [m][k], 80B rows
    __shared__ __align__(16) __half Bs2[KC][HID + 8];  // [k][n], 144B rows
    __shared__ float bsh[64];
    int tid = threadIdx.x;
    int warp = tid >> 5, lane = tid & 31;
    int g = lane >> 2;
    int t2 = (lane & 3) * 2;
    int row0 = blockIdx.x * 64;

    if (tid < 64) bsh[tid] = b1[tid];

    // ldmatrix source addresses
    // A x4: lanes 0-7 -> rows of (m0-7,k0-7), 8-15 -> (m8-15,k0-7),
    //       16-23 -> (m0-7,k8-15), 24-31 -> (m8-15,k8-15)
    uint32_t a_base = smem_u32(&As[16 * warp + (lane & 15)][(lane >> 4) << 3]);
    // B x4.trans: lanes 0-7 rows k0-7, 8-15 rows k8-15 (first 8 cols),
    //             16-23 rows k0-7, 24-31 rows k8-15 (next 8 cols)
    int b_krow = (lane & 7) + (lane & 8);
    int b_half = (lane >> 4) & 1;             // 0 -> ntA cols, 1 -> ntB cols

    float acc[8][4];
#pragma unroll
    for (int nt = 0; nt < 8; nt++)
#pragma unroll
        for (int q = 0; q < 4; q++) acc[nt][q] = 0.f;

    for (int kc = 0; kc < INC; kc += KC) {
        // ---- x tile: thread owns row tid>>1, 16 k-values (4 float4, streaming)
        {
            int r = tid >> 1;
            int kp = (tid & 1) * 16;
            int gr = row0 + r;
            const float4* xr = (const float4*)(x + (long long)gr * INC + kc + kp);
            float4 v[4];
#pragma unroll
            for (int q = 0; q < 4; q++)
                v[q] = (gr < NN) ? __ldcs(&xr[q]) : make_float4(0.f, 0.f, 0.f, 0.f);
            uint2* dst = (uint2*)&As[r][kp];
#pragma unroll
            for (int q = 0; q < 4; q++) {
                __half2 h0 = __floats2half2_rn(v[q].x, v[q].y);
                __half2 h1 = __floats2half2_rn(v[q].z, v[q].w);
                dst[q] = make_uint2(h2_bits(h0), h2_bits(h1));
            }
        }
        // ---- W1 chunk: [k][n] untransposed, vector stores
#pragma unroll
        for (int q = 0; q < 4; q++) {
            int idx = tid + 128 * q;              // 0..511 float4s
            int k = idx >> 4;
            int n0 = (idx & 15) * 4;
            float4 wv = *(const float4*)(W1 + (long long)(kc + k) * HID + n0);
            __half2 h0 = __floats2half2_rn(wv.x, wv.y);
            __half2 h1 = __floats2half2_rn(wv.z, wv.w);
            *(uint2*)&Bs2[k][n0] = make_uint2(h2_bits(h0), h2_bits(h1));
        }
        __syncthreads();

#pragma unroll
        for (int kk = 0; kk < KC; kk += 16) {
            uint32_t a0, a1, a2, a3;
            asm volatile(
                "ldmatrix.sync.aligned.m8n8.x4.shared.b16 {%0,%1,%2,%3}, [%4];"
                : "=r"(a0), "=r"(a1), "=r"(a2), "=r"(a3)
                : "r"(a_base + (uint32_t)(kk * 2)));
#pragma unroll
            for (int p = 0; p < 4; p++) {
                uint32_t b0A, b1A, b0B, b1B;
                uint32_t b_addr = smem_u32(&Bs2[kk + b_krow][(2 * p + b_half) * 8]);
                asm volatile(
                    "ldmatrix.sync.aligned.m8n8.x4.trans.shared.b16 {%0,%1,%2,%3}, [%4];"
                    : "=r"(b0A), "=r"(b1A), "=r"(b0B), "=r"(b1B)
                    : "r"(b_addr));
                asm volatile(
                    "mma.sync.aligned.m16n8k16.row.col.f32.f16.f16.f32 "
                    "{%0,%1,%2,%3}, {%4,%5,%6,%7}, {%8,%9}, {%0,%1,%2,%3};"
                    : "+f"(acc[2 * p][0]), "+f"(acc[2 * p][1]),
                      "+f"(acc[2 * p][2]), "+f"(acc[2 * p][3])
                    : "r"(a0), "r"(a1), "r"(a2), "r"(a3), "r"(b0A), "r"(b1A));
                asm volatile(
                    "mma.sync.aligned.m16n8k16.row.col.f32.f16.f16.f32 "
                    "{%0,%1,%2,%3}, {%4,%5,%6,%7}, {%8,%9}, {%0,%1,%2,%3};"
                    : "+f"(acc[2 * p + 1][0]), "+f"(acc[2 * p + 1][1]),
                      "+f"(acc[2 * p + 1][2]), "+f"(acc[2 * p + 1][3])
                    : "r"(a0), "r"(a1), "r"(a2), "r"(a3), "r"(b0B), "r"(b1B));
            }
        }
        __syncthreads();
    }

    int r1 = row0 + 16 * warp + g;
    int r2 = r1 + 8;
    float dv1 = (r1 < NN) ? g_dinv[r1] : 0.f;
    float dv2 = (r2 < NN) ? g_dinv[r2] : 0.f;
#pragma unroll
    for (int nt = 0; nt < 8; nt++) {
        int c0 = nt * 8 + t2;
        float bb0 = bsh[c0], bb1 = bsh[c0 + 1];
        if (r1 < NN) {
            float h0 = fmaxf(acc[nt][0] + bb0, 0.f);
            float h1 = fmaxf(acc[nt][1] + bb1, 0.f);
            g_H[0][r1 * 32 + (c0 >> 1)] = __floats2half2_rn(dv1 * h0, dv1 * h1);
        }
        if (r2 < NN) {
            float h0 = fmaxf(acc[nt][2] + bb0, 0.f);
            float h1 = fmaxf(acc[nt][3] + bb1, 0.f);
            g_H[0][r2 * 32 + (c0 >> 1)] = __floats2half2_rn(dv2 * h0, dv2 * h1);
        }
    }
}

// ======================= Jacobi propagation (hot loop) ===================
// EXACT R13/R11 form — measured local optimum (MLP depth, block shape,
// permutation, value pipelining, cache hints all regress it).

__device__ __forceinline__ void gather8(const __half2* __restrict__ g,
                                        const int* __restrict__ src,
                                        int s, int e, int lane,
                                        float& gx, float& gy) {
    float a0x = 0.f, a0y = 0.f, a1x = 0.f, a1y = 0.f;
    float a2x = 0.f, a2y = 0.f, a3x = 0.f, a3y = 0.f;
    int4 ia = *(const int4*)(src + s);
    int4 ib = *(const int4*)(src + s + 4);
    for (int j = s; j < e; j += 8) {
        // prefetch next iteration's indices (safe over-read: capacity slack)
        int4 na = *(const int4*)(src + j + 8);
        int4 nb = *(const int4*)(src + j + 12);
        float2 v0 = __half22float2(g[ia.x * 32 + lane]);
        float2 v1 = __half22float2(g[ia.y * 32 + lane]);
        float2 v2 = __half22float2(g[ia.z * 32 + lane]);
        float2 v3 = __half22float2(g[ia.w * 32 + lane]);
        float2 v4 = __half22float2(g[ib.x * 32 + lane]);
        float2 v5 = __half22float2(g[ib.y * 32 + lane]);
        float2 v6 = __half22float2(g[ib.z * 32 + lane]);
        float2 v7 = __half22float2(g[ib.w * 32 + lane]);
        a0x += v0.x + v4.x; a0y += v0.y + v4.y;
        a1x += v1.x + v5.x; a1y += v1.y + v5.y;
        a2x += v2.x + v6.x; a2y += v2.y + v6.y;
        a3x += v3.x + v7.x; a3y += v3.y + v7.y;
        ia = na; ib = nb;
    }
    gx = (a0x + a1x) + (a2x + a3x);
    gy = (a0y + a1y) + (a2y + a3y);
}

__global__ __launch_bounds__(128) void prop_first_kernel() {
    int w = threadIdx.x >> 5, lane = threadIdx.x & 31;
    int node = blockIdx.x * 4 + w;
    if (node >= NN) return;
    const __half2* __restrict__ g = g_H[0];
    __half2* __restrict__ go = g_H[1];

    int idx2 = node * 32 + lane;
    float2 self = __half22float2(g[idx2]);
    float gx, gy;
    gather8(g, g_src, g_off[node], g_off[node + 1], lane, gx, gy);
    gx += self.x; gy += self.y;                // self loop
    float dv = g_dinv[node];
    float dv2f = dv * dv;
    go[idx2] = __floats2half2_rn(dv2f * gx, dv2f * gy);
}

__global__ __launch_bounds__(128) void prop_step_kernel(float An, float Bn, float Cn,
                                                        int kin, int kt0, int kout) {
    int w = threadIdx.x >> 5, lane = threadIdx.x & 31;
    int node = blockIdx.x * 4 + w;
    if (node >= NN) return;
    const __half2* __restrict__ g = g_H[kin];
    const __half2* __restrict__ gt0 = g_H[kt0];
    __half2* __restrict__ go = g_H[kout];

    int idx2 = node * 32 + lane;
    float2 self = __half22float2(g[idx2]);     // dinv * t1
    float2 g0 = __half22float2(__ldcs(&gt0[idx2]));  // dinv * t0 (evict-first;
                                               // not re-read before overwrite)
    float gx, gy;
    gather8(g, g_src, g_off[node], g_off[node + 1], lane, gx, gy);
    gx += self.x; gy += self.y;                // self loop

    float dv = g_dinv[node], ds = g_ds[node];
    float px = dv * gx, py = dv * gy;          // (P t1)
    float t1x = self.x * ds, t1y = self.y * ds;
    float t0x = g0.x * ds, t0y = g0.y * ds;
    float t2x = An * px + Bn * t1x - Cn * t0x;
    float t2y = An * py + Bn * t1y - Cn * t0y;
    go[idx2] = __floats2half2_rn(dv * t2x, dv * t2y);
}

// ======================= layer epilogue (vectorized) =====================
// slot0' = relu(sum_k c_k slot_k).  Thread handles 4 half2 = 8 channels.
__global__ void layer_epi_kernel(const float* __restrict__ coeffs, int base) {
    int i = blockIdx.x * 256 + threadIdx.x;     // int4 item: node=i>>3, 8 ch
    if (i >= NN * 8) return;
    float c[KORD + 1];
#pragma unroll
    for (int k = 0; k <= KORD; k++) c[k] = coeffs[base + k];
    int off = i * 4;                            // half2 offset (16B aligned)
    float ax[4] = {0.f, 0.f, 0.f, 0.f};
    float ay[4] = {0.f, 0.f, 0.f, 0.f};
#pragma unroll
    for (int k = 0; k <= KORD; k++) {
        int4 raw = *(const int4*)&g_H[k][off];
        const __half2* h = (const __half2*)&raw;
#pragma unroll
        for (int q = 0; q < 4; q++) {
            float2 v = __half22float2(h[q]);
            ax[q] += c[k] * v.x;
            ay[q] += c[k] * v.y;
        }
    }
    int4 outw;
    __half2* ho = (__half2*)&outw;
#pragma unroll
    for (int q = 0; q < 4; q++)
        ho[q] = __floats2half2_rn(fmaxf(ax[q], 0.f), fmaxf(ay[q], 0.f));
    *(int4*)&g_H[0][off] = outw;
}

// ============== fused layer-2 epilogue + GEMM2 ===========================
__global__ __launch_bounds__(256) void epi_gemm2_kernel(const float* __restrict__ coeffs,
                                                        int base,
                                                        const float* __restrict__ W2,
                                                        const float* __restrict__ b2,
                                                        float* __restrict__ out) {
    __shared__ __align__(16) float ws[64][32];
    __shared__ __align__(16) float xs[32][65];
    int tid = threadIdx.x;
    int row0 = blockIdx.x * 32;

    for (int l = tid; l < 64 * 32; l += 256) ws[l >> 5][l & 31] = W2[l];

    {
        float c[KORD + 1];
#pragma unroll
        for (int k = 0; k <= KORD; k++) c[k] = coeffs[base + k];
        int r = tid >> 3;
        int kk0 = (tid & 7) * 4;
        int gr = row0 + r;
        int off = gr * 32 + kk0;
        float ax[4] = {0.f, 0.f, 0.f, 0.f};
        float ay[4] = {0.f, 0.f, 0.f, 0.f};
#pragma unroll
        for (int k = 0; k <= KORD; k++) {
            int4 raw = *(const int4*)&g_H[k][off];
            const __half2* h = (const __half2*)&raw;
#pragma unroll
            for (int q = 0; q < 4; q++) {
                float2 v = __half22float2(h[q]);
                ax[q] += c[k] * v.x;
                ay[q] += c[k] * v.y;
            }
        }
        float dsv = g_ds[gr];
#pragma unroll
        for (int q = 0; q < 4; q++) {
            xs[r][(kk0 + q) * 2]     = dsv * fmaxf(ax[q], 0.f);
            xs[r][(kk0 + q) * 2 + 1] = dsv * fmaxf(ay[q], 0.f);
        }
    }
    __syncthreads();

    int tx = tid & 31;
    int ty = tid >> 5;
    float acc[4] = {0.f, 0.f, 0.f, 0.f};
#pragma unroll
    for (int k = 0; k < 64; k++) {
        float wv = ws[k][tx];
#pragma unroll
        for (int i = 0; i < 4; i++) acc[i] += xs[ty * 4 + i][k] * wv;
    }
    float bb = b2[tx];
#pragma unroll
    for (int i = 0; i < 4; i++) {
        int gr = row0 + ty * 4 + i;
        out[gr * OUTC + tx] = acc[i] + bb;
    }
}

// ======================= launcher =======================

extern "C" void kernel_launch(void* const* d_in, const int* in_sizes, int n_in,
                              void* d_out, int out_size) {
    const float* x      = (const float*)d_in[0];
    const void*  ei     = d_in[1];
    const float* W1     = (const float*)d_in[2];
    const float* b1     = (const float*)d_in[3];
    const float* coeffs = (const float*)d_in[4];
    const float* W2     = (const float*)d_in[5];
    const float* b2     = (const float*)d_in[6];
    float*       out    = (float*)d_out;

    // one-time host resources (no device memory; device work stays identical)
    static cudaStream_t s2 = nullptr;
    static cudaEvent_t evFork = nullptr, evJoin = nullptr;
    if (s2 == nullptr) {
        cudaStreamCreateWithFlags(&s2, cudaStreamNonBlocking);
        cudaEventCreateWithFlags(&evFork, cudaEventDisableTiming);
        cudaEventCreateWithFlags(&evJoin, cudaEventDisableTiming);
    }

    zero_detect_kernel<<<(NEP_MAX / 4 + 255) / 256, 256>>>((const int*)ei);
    count_deg_kernel<<<(NE / 4 + 255) / 256, 256>>>(ei);
    scan1_kernel<<<NBLK_SCAN, 256>>>();

    // fork: gemm1 (needs only dinv) runs on s2, overlapped with scan23+scatter
    cudaEventRecord(evFork, 0);
    cudaStreamWaitEvent(s2, evFork, 0);
    gemm1_kernel<<<(NN + 63) / 64, 128, 0, s2>>>(x, W1, b1);
    cudaEventRecord(evJoin, s2);

    scan23_kernel<<<(NN + 511) / 512, 512>>>();
    scatter_kernel<<<(NE / 4 + 255) / 256, 256>>>(ei);

    // join: props need both CSR (default stream) and g_H[0] (s2)
    cudaStreamWaitEvent(0, evJoin, 0);

    const double a = 0.5, b = 0.5;
    for (int l = 0; l < NLAYERS; l++) {
        prop_first_kernel<<<NBLK_PROP, 128>>>();
        for (int k = 2; k <= KORD; k++) {
            double n = (double)(k - 1);
            double An = (2 * n + a + b + 1) * (2 * n + a + b + 2)
                        / (2 * (n + 1) * (n + a + b + 1));
            double Bn = (a * a - b * b) * (2 * n + a + b + 1)
                        / (2 * (n + 1) * (n + a + b + 1) * (2 * n + a + b));
            double Cn = (n + a) * (n + b) * (2 * n + a + b + 2)
                        / ((n + 1) * (n + a + b + 1) * (2 * n + a + b));
            prop_step_kernel<<<NBLK_PROP, 128>>>((float)An, (float)Bn, (float)Cn,
                                                 k - 1, k - 2, k);
        }
        if (l == 0)
            layer_epi_kernel<<<(NN * 8 + 255) / 256, 256>>>(coeffs, 0);
        else
            epi_gemm2_kernel<<<NN / 32, 256>>>(coeffs, KORD + 1, W2, b2, out);
    }
}